// round 17
// baseline (speedup 1.0000x reference)
#include <cuda_runtime.h>
#include <cuda_bf16.h>
#include <math.h>
#include <stdint.h>

// Problem constants
#define BB 4
#define LL 2048
#define DM 1024
#define NH 16
#define DH 64
#define MM (BB*LL)          // 8192 rows
#define ELEMS (MM*DM)       // 8388608
#define WELEMS (DM*DM)      // 1048576

// Scratch (float units): xn bf16 @0, q bf16 @1E, k bf16 @2E, vt bf16 @3E,
// attn bf16 @4E, weights bf16 @5E (2*WELEMS floats), rope table after.
__device__ float g_scratch[5 * (size_t)ELEMS + 4 * (size_t)WELEMS + 131072];

#define PACK_BF16X2(r, lo, hi) \
    asm("cvt.rn.bf16x2.f32 %0, %1, %2;" : "=r"(r) : "f"(hi), "f"(lo))
__device__ __forceinline__ uint32_t fau(float f) { return __float_as_uint(f); }
__device__ __forceinline__ float uaf(uint32_t u) { return __uint_as_float(u); }

__device__ __forceinline__ void mma_bf16(float c[4],
                                         const uint32_t a[4],
                                         const uint32_t b[2]) {
    asm volatile(
        "mma.sync.aligned.m16n8k16.row.col.f32.bf16.bf16.f32 "
        "{%0,%1,%2,%3}, {%4,%5,%6,%7}, {%8,%9}, {%0,%1,%2,%3};\n"
        : "+f"(c[0]), "+f"(c[1]), "+f"(c[2]), "+f"(c[3])
        : "r"(a[0]), "r"(a[1]), "r"(a[2]), "r"(a[3]),
          "r"(b[0]), "r"(b[1]));
}

__device__ __forceinline__ void ldmx4(uint32_t& r0, uint32_t& r1,
                                      uint32_t& r2, uint32_t& r3,
                                      uint32_t addr) {
    asm volatile("ldmatrix.sync.aligned.m8n8.x4.shared.b16 {%0,%1,%2,%3}, [%4];"
                 : "=r"(r0), "=r"(r1), "=r"(r2), "=r"(r3) : "r"(addr));
}

#define CP_ASYNC16(dst, src) \
    asm volatile("cp.async.cg.shared.global [%0], [%1], 16;\n" \
                 :: "r"(dst), "l"(src) : "memory")
#define CP_ASYNC16_CA(dst, src) \
    asm volatile("cp.async.ca.shared.global [%0], [%1], 16;\n" \
                 :: "r"(dst), "l"(src) : "memory")
#define CP_COMMIT() asm volatile("cp.async.commit_group;\n" ::: "memory")
#define CP_WAIT2()  asm volatile("cp.async.wait_group 2;\n" ::: "memory")
#define CP_WAIT1()  asm volatile("cp.async.wait_group 1;\n" ::: "memory")
#define CP_WAIT0()  asm volatile("cp.async.wait_group 0;\n" ::: "memory")

// ---------------------------------------------------------------------------
// Weight prep (merged): fp32 [k][n] -> bf16 transposed [n][k], 4 matrices
// ---------------------------------------------------------------------------
__global__ __launch_bounds__(256) void cvtwt4_kernel(const float* __restrict__ W0,
                                                     const float* __restrict__ W1,
                                                     const float* __restrict__ W2,
                                                     const float* __restrict__ W3,
                                                     __nv_bfloat16* __restrict__ dstc) {
    __shared__ float tile[32][33];
    const int tx = threadIdx.x, ty = threadIdx.y;
    const int bx = blockIdx.x, by = blockIdx.y, bz = blockIdx.z;
    const float* src = (bz == 0) ? W0 : (bz == 1) ? W1 : (bz == 2) ? W2 : W3;
    __nv_bfloat16* dst = dstc + (size_t)bz * WELEMS;
#pragma unroll
    for (int i = 0; i < 4; i++) {
        const int k = by * 32 + ty + i * 8;
        tile[ty + i * 8][tx] = src[(size_t)k * DM + bx * 32 + tx];
    }
    __syncthreads();
#pragma unroll
    for (int i = 0; i < 4; i++) {
        const int n = bx * 32 + ty + i * 8;
        dst[(size_t)n * DM + by * 32 + tx] = __float2bfloat16_rn(tile[tx][ty + i * 8]);
    }
}

// ---------------------------------------------------------------------------
// RoPE cos/sin table
// ---------------------------------------------------------------------------
__global__ __launch_bounds__(256) void rope_table_kernel(float2* __restrict__ t) {
    const int idx = blockIdx.x * 256 + threadIdx.x;   // 65536
    const int l = idx >> 5, p = idx & 31;
    const float inv = exp2f((float)p * (-2.0f / 64.0f) * 13.2877123795494f);
    float s, c;
    sincosf((float)l * inv, &s, &c);
    t[idx] = make_float2(c, s);
}

// ---------------------------------------------------------------------------
// LayerNorm -> bf16
// ---------------------------------------------------------------------------
__global__ __launch_bounds__(256) void ln_kernel(const float* __restrict__ x,
                                                 const float* __restrict__ gamma,
                                                 const float* __restrict__ beta,
                                                 __nv_bfloat16* __restrict__ xn) {
    const int row = blockIdx.x;
    const int t = threadIdx.x;
    const float4 v = ((const float4*)(x + (size_t)row * DM))[t];
    __shared__ float red[8];

    float s = v.x + v.y + v.z + v.w;
#pragma unroll
    for (int o = 16; o > 0; o >>= 1) s += __shfl_xor_sync(0xffffffffu, s, o);
    if ((t & 31) == 0) red[t >> 5] = s;
    __syncthreads();
    float mean = (red[0]+red[1]+red[2]+red[3]+red[4]+red[5]+red[6]+red[7]) * (1.0f/DM);

    float dx = v.x-mean, dy = v.y-mean, dz = v.z-mean, dw = v.w-mean;
    float q = dx*dx + dy*dy + dz*dz + dw*dw;
#pragma unroll
    for (int o = 16; o > 0; o >>= 1) q += __shfl_xor_sync(0xffffffffu, q, o);
    __syncthreads();
    if ((t & 31) == 0) red[t >> 5] = q;
    __syncthreads();
    float var = (red[0]+red[1]+red[2]+red[3]+red[4]+red[5]+red[6]+red[7]) * (1.0f/DM);
    float rs = rsqrtf(var + 1e-5f);

    const float4 g4 = ((const float4*)gamma)[t];
    const float4 b4 = ((const float4*)beta)[t];
    uint32_t p0, p1;
    PACK_BF16X2(p0, dx*rs*g4.x + b4.x, dy*rs*g4.y + b4.y);
    PACK_BF16X2(p1, dz*rs*g4.z + b4.z, dw*rs*g4.w + b4.w);
    *(uint2*)((char*)xn + ((size_t)row * DM + 4 * t) * 2) = make_uint2(p0, p1);
}

// ---------------------------------------------------------------------------
// bf16 GEMM core: 256x128x32 CTA tile, 16 warps (4Mx4N), 512 threads,
// 4-stage cp.async, ldmatrix.x4 full preload + 64-mma burst per warp.
// Rows 80B stride. A stage 20480B x4 @0; B stage 10240B x4 @81920.
// Total smem 122880B. 1 CTA/SM (64K regs exactly).
// ---------------------------------------------------------------------------
#define GSTG_A 20480
#define GSTG_B 10240
#define GB_BASE 81920
#define GSMEM 122880

struct GemmCore {
    int tid, lane, warp, warpM, warpN, g, l4;
    uint32_t smbase;
    const __nv_bfloat16* Ab;
    const __nv_bfloat16* Bb;
    uint32_t aoff, boff;
    float acc[16][4];

    __device__ __forceinline__ void init(char* sm, const __nv_bfloat16* A_,
                                         const __nv_bfloat16* B_) {
        tid = threadIdx.x; lane = tid & 31; warp = tid >> 5;
        warpM = warp >> 2; warpN = warp & 3;     // 4 x 4
        g = lane >> 2; l4 = lane & 3;
        smbase = (uint32_t)__cvta_generic_to_shared(sm);
        Ab = A_; Bb = B_;
        aoff = (uint32_t)(warpM * 64 + (lane & 15)) * 80 + (lane >> 4) * 16;
        boff = (uint32_t)(warpN * 32 + ((lane >> 4) << 3) + (lane & 7)) * 80
             + ((lane >> 3) & 1) * 16;
#pragma unroll
        for (int i = 0; i < 16; i++)
#pragma unroll
            for (int j = 0; j < 4; j++) acc[i][j] = 0.f;
    }

    __device__ __forceinline__ void issue(int stage, int k0) {
        // A: 256 rows x 2 16B chunks -> 512 threads x 2 chunks
        const int arow = tid >> 1;
        const int ac2 = (tid & 1) * 2;
#pragma unroll
        for (int c = ac2; c < ac2 + 2; c++)
            CP_ASYNC16(smbase + stage * GSTG_A + arow * 80 + c * 16,
                       Ab + (size_t)arow * 1024 + k0 + c * 8);
        // B: 128 rows x 4 chunks -> 512 threads x 1 chunk
        const int brow = tid >> 2;
        const int bc = tid & 3;
        CP_ASYNC16(smbase + GB_BASE + stage * GSTG_B + brow * 80 + bc * 16,
                   Bb + (size_t)brow * 1024 + k0 + bc * 8);
    }

    __device__ __forceinline__ void compute(int stage) {
        const uint32_t Asb = smbase + stage * GSTG_A + aoff;
        const uint32_t Bsb = smbase + GB_BASE + stage * GSTG_B + boff;
        uint32_t af[2][4][4];
        uint32_t bf[2][4][2];
#pragma unroll
        for (int kh = 0; kh < 2; kh++) {
            const int ko = kh * 32;
#pragma unroll
            for (int i = 0; i < 4; i++)
                ldmx4(af[kh][i][0], af[kh][i][1], af[kh][i][2], af[kh][i][3],
                      Asb + i * (16 * 80) + ko);
#pragma unroll
            for (int jj = 0; jj < 2; jj++)
                ldmx4(bf[kh][2*jj][0], bf[kh][2*jj][1],
                      bf[kh][2*jj+1][0], bf[kh][2*jj+1][1],
                      Bsb + jj * (16 * 80) + ko);
        }
#pragma unroll
        for (int kh = 0; kh < 2; kh++)
#pragma unroll
            for (int i = 0; i < 4; i++)
#pragma unroll
                for (int j = 0; j < 4; j++)
                    mma_bf16(acc[i * 4 + j], af[kh][i], bf[kh][j]);
    }

    __device__ __forceinline__ void mainloop() {
        issue(0, 0);   CP_COMMIT();
        issue(1, 32);  CP_COMMIT();
        issue(2, 64);  CP_COMMIT();
        for (int kt = 0; kt < 32; kt++) {
            CP_WAIT2();
            __syncthreads();
            if (kt + 3 < 32) issue((kt + 3) & 3, (kt + 3) * 32);
            CP_COMMIT();
            compute(kt & 3);
        }
    }
};

// ---------------------------------------------------------------------------
// Merged QKV GEMM: grid (24, 32); 256-row tiles. Outputs q,k bf16 (roped,
// q scaled 1/8); v bf16 TRANSPOSED [bh][d][seq].
// ---------------------------------------------------------------------------
__global__ __launch_bounds__(512, 1) void qkv_gemm(const __nv_bfloat16* __restrict__ xn,
                                                   const __nv_bfloat16* __restrict__ Wcat,
                                                   const float* __restrict__ bq,
                                                   const float* __restrict__ bk,
                                                   const float* __restrict__ bv,
                                                   const float2* __restrict__ rtab,
                                                   __nv_bfloat16* __restrict__ qb,
                                                   __nv_bfloat16* __restrict__ kb,
                                                   __nv_bfloat16* __restrict__ vt) {
    extern __shared__ char sm[];
    const int brow = blockIdx.y;
    const int bcol = blockIdx.x;
    const int tsel = bcol >> 3;          // 0=q 1=k 2=v
    const int bcl  = bcol & 7;

    GemmCore core;
    core.init(sm,
              xn + (size_t)brow * 256 * 1024,
              Wcat + (size_t)tsel * WELEMS + (size_t)bcl * 128 * 1024);
    core.mainloop();

    const float* bias = (tsel == 0) ? bq : (tsel == 1) ? bk : bv;
    const float oscale = (tsel == 0) ? 0.125f : 1.0f;

#pragma unroll
    for (int i = 0; i < 4; i++) {
        const int r0 = brow * 256 + core.warpM * 64 + i * 16 + core.g;
        const int l0 = r0 & (LL - 1);
        const int bidx = r0 >> 11;
#pragma unroll
        for (int j = 0; j < 4; j++) {
            const int cc = bcl * 128 + core.warpN * 32 + j * 8 + (core.l4 << 1);
            const float bx = bias[cc], by = bias[cc + 1];
            float v0x = core.acc[i * 4 + j][0] + bx;
            float v0y = core.acc[i * 4 + j][1] + by;
            float v1x = core.acc[i * 4 + j][2] + bx;
            float v1y = core.acc[i * 4 + j][3] + by;
            if (tsel < 2) {
                const int p = (cc & 63) >> 1;
                const float2 cs0 = rtab[l0 * 32 + p];
                const float2 cs1 = rtab[(l0 + 8) * 32 + p];
                float t;
                t   = v0x * cs0.x - v0y * cs0.y;
                v0y = v0x * cs0.y + v0y * cs0.x;
                v0x = t;
                t   = v1x * cs1.x - v1y * cs1.y;
                v1y = v1x * cs1.y + v1y * cs1.x;
                v1x = t;
                uint32_t p0, p1;
                PACK_BF16X2(p0, v0x * oscale, v0y * oscale);
                PACK_BF16X2(p1, v1x * oscale, v1y * oscale);
                __nv_bfloat16* C = (tsel == 0) ? qb : kb;
                *(uint32_t*)((char*)C + ((size_t)r0 * 1024 + cc) * 2)       = p0;
                *(uint32_t*)((char*)C + ((size_t)(r0 + 8) * 1024 + cc) * 2) = p1;
            } else {
                const int h = cc >> 6, d = cc & 63;
                __nv_bfloat16* row0 = vt + ((size_t)(bidx * 16 + h) * 64 + d) * LL;
                __nv_bfloat16* row1 = row0 + LL;
                row0[l0]     = __float2bfloat16_rn(v0x);
                row1[l0]     = __float2bfloat16_rn(v0y);
                row0[l0 + 8] = __float2bfloat16_rn(v1x);
                row1[l0 + 8] = __float2bfloat16_rn(v1y);
            }
        }
    }
}

// ---------------------------------------------------------------------------
// Output projection GEMM: grid (8, 32). out = attn @ Wot^T + bo + x (fp32)
// ---------------------------------------------------------------------------
__global__ __launch_bounds__(512, 1) void o_gemm(const __nv_bfloat16* __restrict__ A,
                                                 const __nv_bfloat16* __restrict__ Wt,
                                                 const float* __restrict__ bias,
                                                 const float* __restrict__ resid,
                                                 float* __restrict__ C) {
    extern __shared__ char sm[];
    const int brow = blockIdx.y;
    const int bcol = blockIdx.x;

    GemmCore core;
    core.init(sm, A + (size_t)brow * 256 * 1024, Wt + (size_t)bcol * 128 * 1024);
    core.mainloop();

#pragma unroll
    for (int i = 0; i < 4; i++) {
        const int r0 = brow * 256 + core.warpM * 64 + i * 16 + core.g;
#pragma unroll
        for (int j = 0; j < 4; j++) {
            const int cc = bcol * 128 + core.warpN * 32 + j * 8 + (core.l4 << 1);
            const float bx = bias[cc], by = bias[cc + 1];
            const float2 r0v = *(const float2*)(resid + (size_t)r0 * 1024 + cc);
            const float2 r1v = *(const float2*)(resid + (size_t)(r0 + 8) * 1024 + cc);
            *(float2*)(C + (size_t)r0 * 1024 + cc) =
                make_float2(core.acc[i*4+j][0] + bx + r0v.x,
                            core.acc[i*4+j][1] + by + r0v.y);
            *(float2*)(C + (size_t)(r0 + 8) * 1024 + cc) =
                make_float2(core.acc[i*4+j][2] + bx + r1v.x,
                            core.acc[i*4+j][3] + by + r1v.y);
        }
    }
}

// ---------------------------------------------------------------------------
// bf16 flash attention (causal) — unchanged from R16 best.
// ---------------------------------------------------------------------------
#define QROW 144
#define KV_STG (64 * QROW)
#define SK_BASE 18432
#define SV_BASE (SK_BASE + 2 * KV_STG)
#define ASMEM (SV_BASE + 2 * KV_STG)   // 55296

__global__ __launch_bounds__(128) void attn_tc_kernel(const __nv_bfloat16* __restrict__ qg,
                                                      const __nv_bfloat16* __restrict__ kg,
                                                      const __nv_bfloat16* __restrict__ vt,
                                                      __nv_bfloat16* __restrict__ og) {
    extern __shared__ char sma[];
    const uint32_t smbase = (uint32_t)__cvta_generic_to_shared(sma);

    const int bh = blockIdx.y;
    const int b = bh >> 4, h = bh & 15;
    const int qt = (int)gridDim.x - 1 - (int)blockIdx.x;
    const int qbase = qt * 128;
    const int tid  = threadIdx.x;
    const int lane = tid & 31;
    const int warp = tid >> 5;
    const int g  = lane >> 2;
    const int l4 = lane & 3;

#pragma unroll
    for (int it = 0; it < 8; it++) {
        const int i = tid + it * 128;
        const int row = i >> 3, c = i & 7;
        CP_ASYNC16_CA(smbase + row * QROW + c * 16,
                      qg + (size_t)(b * LL + qbase + row) * 1024 + h * 64 + c * 8);
    }

    auto issueKV = [&](int t64, int st) {
#pragma unroll
        for (int it = 0; it < 4; it++) {
            const int i = tid + it * 128;
            const int row = i >> 3, c = i & 7;
            CP_ASYNC16_CA(smbase + SK_BASE + st * KV_STG + row * QROW + c * 16,
                          kg + (size_t)(b * LL + t64 * 64 + row) * 1024 + h * 64 + c * 8);
            CP_ASYNC16_CA(smbase + SV_BASE + st * KV_STG + row * QROW + c * 16,
                          vt + ((size_t)(bh * 64 + row)) * LL + t64 * 64 + c * 8);
        }
    };

    float s[2][8][4];
    float o[2][8][4];
#pragma unroll
    for (int mt = 0; mt < 2; mt++)
#pragma unroll
        for (int n = 0; n < 8; n++)
#pragma unroll
            for (int i = 0; i < 4; i++) o[mt][n][i] = 0.f;
    float mrow[4] = {-1e30f, -1e30f, -1e30f, -1e30f};
    float lrow[4] = {0.f, 0.f, 0.f, 0.f};

    const int ntiles = 2 * qt + 2;
    issueKV(0, 0);
    CP_COMMIT();

    for (int t64 = 0; t64 < ntiles; t64++) {
        const int st = t64 & 1;
        __syncthreads();
        if (t64 + 1 < ntiles) {
            issueKV(t64 + 1, st ^ 1);
            CP_COMMIT();
            CP_WAIT1();
        } else {
            CP_WAIT0();
        }
        __syncthreads();

        const char* Kst = sma + SK_BASE + st * KV_STG;
        const char* Vst = sma + SV_BASE + st * KV_STG;
        const int j0 = t64 * 64;

#pragma unroll
        for (int mt = 0; mt < 2; mt++)
#pragma unroll
            for (int n = 0; n < 8; n++)
#pragma unroll
                for (int i = 0; i < 4; i++) s[mt][n][i] = 0.f;

#pragma unroll
        for (int kk = 0; kk < 4; kk++) {
            uint32_t qa[2][4];
#pragma unroll
            for (int mt = 0; mt < 2; mt++) {
                const char* qp = sma + (warp * 32 + mt * 16 + g) * QROW + kk * 32 + l4 * 4;
                qa[mt][0] = *(const uint32_t*)(qp);
                qa[mt][1] = *(const uint32_t*)(qp + 8 * QROW);
                qa[mt][2] = *(const uint32_t*)(qp + 16);
                qa[mt][3] = *(const uint32_t*)(qp + 8 * QROW + 16);
            }
#pragma unroll
            for (int n = 0; n < 8; n++) {
                uint32_t kb[2];
                const char* kp = Kst + (n * 8 + g) * QROW + kk * 32 + l4 * 4;
                kb[0] = *(const uint32_t*)(kp);
                kb[1] = *(const uint32_t*)(kp + 16);
                mma_bf16(s[0][n], qa[0], kb);
                mma_bf16(s[1][n], qa[1], kb);
            }
        }

        if (t64 >= 2 * qt) {
#pragma unroll
            for (int mt = 0; mt < 2; mt++) {
                const int rg = qbase + warp * 32 + mt * 16 + g;
#pragma unroll
                for (int n = 0; n < 8; n++) {
                    const int c0 = j0 + n * 8 + 2 * l4;
                    if (c0     > rg)     s[mt][n][0] = -1e30f;
                    if (c0 + 1 > rg)     s[mt][n][1] = -1e30f;
                    if (c0     > rg + 8) s[mt][n][2] = -1e30f;
                    if (c0 + 1 > rg + 8) s[mt][n][3] = -1e30f;
                }
            }
        }

#pragma unroll
        for (int mt = 0; mt < 2; mt++) {
            float r0 = -1e30f, r1 = -1e30f;
#pragma unroll
            for (int n = 0; n < 8; n++) {
                r0 = fmaxf(r0, fmaxf(s[mt][n][0], s[mt][n][1]));
                r1 = fmaxf(r1, fmaxf(s[mt][n][2], s[mt][n][3]));
            }
            r0 = fmaxf(r0, __shfl_xor_sync(0xffffffffu, r0, 1));
            r0 = fmaxf(r0, __shfl_xor_sync(0xffffffffu, r0, 2));
            r1 = fmaxf(r1, __shfl_xor_sync(0xffffffffu, r1, 1));
            r1 = fmaxf(r1, __shfl_xor_sync(0xffffffffu, r1, 2));
            const float m0 = fmaxf(mrow[2*mt],   r0);
            const float m1 = fmaxf(mrow[2*mt+1], r1);
            const float c0 = __expf(mrow[2*mt]   - m0);
            const float c1 = __expf(mrow[2*mt+1] - m1);
            mrow[2*mt] = m0; mrow[2*mt+1] = m1;
            float ps0 = 0.f, ps1 = 0.f;
#pragma unroll
            for (int n = 0; n < 8; n++) {
                s[mt][n][0] = __expf(s[mt][n][0] - m0);
                s[mt][n][1] = __expf(s[mt][n][1] - m0);
                s[mt][n][2] = __expf(s[mt][n][2] - m1);
                s[mt][n][3] = __expf(s[mt][n][3] - m1);
                ps0 += s[mt][n][0] + s[mt][n][1];
                ps1 += s[mt][n][2] + s[mt][n][3];
                o[mt][n][0] *= c0; o[mt][n][1] *= c0;
                o[mt][n][2] *= c1; o[mt][n][3] *= c1;
            }
            lrow[2*mt]   = lrow[2*mt]   * c0 + ps0;
            lrow[2*mt+1] = lrow[2*mt+1] * c1 + ps1;
        }

#pragma unroll
        for (int kk = 0; kk < 4; kk++) {
            uint32_t pa[2][4];
#pragma unroll
            for (int mt = 0; mt < 2; mt++) {
                PACK_BF16X2(pa[mt][0], s[mt][2*kk][0],   s[mt][2*kk][1]);
                PACK_BF16X2(pa[mt][1], s[mt][2*kk][2],   s[mt][2*kk][3]);
                PACK_BF16X2(pa[mt][2], s[mt][2*kk+1][0], s[mt][2*kk+1][1]);
                PACK_BF16X2(pa[mt][3], s[mt][2*kk+1][2], s[mt][2*kk+1][3]);
            }
#pragma unroll
            for (int nd = 0; nd < 8; nd++) {
                uint32_t vb[2];
                const char* vp = Vst + (nd * 8 + g) * QROW + kk * 32 + l4 * 4;
                vb[0] = *(const uint32_t*)(vp);
                vb[1] = *(const uint32_t*)(vp + 16);
                mma_bf16(o[0][nd], pa[0], vb);
                mma_bf16(o[1][nd], pa[1], vb);
            }
        }
    }

#pragma unroll
    for (int i = 0; i < 4; i++) {
        lrow[i] += __shfl_xor_sync(0xffffffffu, lrow[i], 1);
        lrow[i] += __shfl_xor_sync(0xffffffffu, lrow[i], 2);
        lrow[i] = 1.0f / lrow[i];
    }
#pragma unroll
    for (int mt = 0; mt < 2; mt++) {
        const int rg = b * LL + qbase + warp * 32 + mt * 16 + g;
#pragma unroll
        for (int n = 0; n < 8; n++) {
            const size_t a0 = (size_t)rg * 1024 + h * 64 + n * 8 + 2 * l4;
            uint32_t p0, p1;
            PACK_BF16X2(p0, o[mt][n][0] * lrow[2*mt],   o[mt][n][1] * lrow[2*mt]);
            PACK_BF16X2(p1, o[mt][n][2] * lrow[2*mt+1], o[mt][n][3] * lrow[2*mt+1]);
            *(uint32_t*)((char*)og + a0 * 2)              = p0;
            *(uint32_t*)((char*)og + (a0 + 8 * 1024) * 2) = p1;
        }
    }
}

// ---------------------------------------------------------------------------
// Launch
// ---------------------------------------------------------------------------
extern "C" void kernel_launch(void* const* d_in, const int* in_sizes, int n_in,
                              void* d_out, int out_size) {
    const float* x     = (const float*)d_in[0];
    const float* gamma = (const float*)d_in[1];
    const float* beta  = (const float*)d_in[2];
    const float* Wq    = (const float*)d_in[3];
    const float* bq    = (const float*)d_in[4];
    const float* Wk    = (const float*)d_in[5];
    const float* bk    = (const float*)d_in[6];
    const float* Wv    = (const float*)d_in[7];
    const float* bv    = (const float*)d_in[8];
    const float* Wo    = (const float*)d_in[9];
    const float* bo    = (const float*)d_in[10];
    float* out = (float*)d_out;

    float* sc = nullptr;
    cudaGetSymbolAddress((void**)&sc, g_scratch);
    __nv_bfloat16* xn   = (__nv_bfloat16*)sc;
    __nv_bfloat16* qb   = (__nv_bfloat16*)(sc + 1 * (size_t)ELEMS);
    __nv_bfloat16* kb   = (__nv_bfloat16*)(sc + 2 * (size_t)ELEMS);
    __nv_bfloat16* vt   = (__nv_bfloat16*)(sc + 3 * (size_t)ELEMS);
    __nv_bfloat16* attn = (__nv_bfloat16*)(sc + 4 * (size_t)ELEMS);
    __nv_bfloat16* Wcat = (__nv_bfloat16*)(sc + 5 * (size_t)ELEMS);  // q,k,v,o
    __nv_bfloat16* Wot  = Wcat + 3 * (size_t)WELEMS;
    float2* rtab = (float2*)(sc + 5 * (size_t)ELEMS + 2 * (size_t)WELEMS);

    cudaFuncSetAttribute(attn_tc_kernel,
                         cudaFuncAttributeMaxDynamicSharedMemorySize, ASMEM);
    cudaFuncSetAttribute(qkv_gemm,
                         cudaFuncAttributeMaxDynamicSharedMemorySize, GSMEM);
    cudaFuncSetAttribute(o_gemm,
                         cudaFuncAttributeMaxDynamicSharedMemorySize, GSMEM);

    rope_table_kernel<<<65536 / 256, 256>>>(rtab);
    dim3 tgrid(32, 32, 4), tblk(32, 8);
    cvtwt4_kernel<<<tgrid, tblk>>>(Wq, Wk, Wv, Wo, Wcat);

    ln_kernel<<<MM, 256>>>(x, gamma, beta, xn);

    dim3 qkvgrid(24, 32);
    qkv_gemm<<<qkvgrid, 512, GSMEM>>>(xn, Wcat, bq, bk, bv, rtab, qb, kb, vt);

    dim3 agrid(LL / 128, BB * NH);
    attn_tc_kernel<<<agrid, 128, ASMEM>>>(qb, kb, vt, attn);

    dim3 ogrid(8, 32);
    o_gemm<<<ogrid, 512, GSMEM>>>(attn, Wot, bo, x, out);
}